// round 1
// baseline (speedup 1.0000x reference)
#include <cuda_runtime.h>

#define NN 50000
#define EE 800000
#define NEG 0.2f
#define EPSV 1e-5f

// ---- scratch (static __device__, no allocations) ----
__device__ float g_xl[NN * 128];
__device__ float g_xr[NN * 128];
__device__ float g_y[NN * 64];
__device__ float g_x[NN * 64];
__device__ int   g_cnt[NN];
__device__ int   g_wofs[NN];
__device__ int   g_rowptr[NN + 1];
__device__ int   g_csrsrc[EE];
__device__ float g_sum[64];
__device__ float g_sumsq[64];

// ---------------- CSR build ----------------
__global__ void k_zero_cnt() {
    int i = blockIdx.x * blockDim.x + threadIdx.x;
    if (i < NN) g_cnt[i] = 0;
}

__global__ void k_hist(const int* __restrict__ dst) {
    int e = blockIdx.x * blockDim.x + threadIdx.x;
    if (e < EE) atomicAdd(&g_cnt[dst[e]], 1);
}

__global__ void k_scan() {
    __shared__ int sT[1024];
    int tid = threadIdx.x;
    const int CH = (NN + 1023) / 1024;
    int base = tid * CH;
    int s = 0;
    for (int i = 0; i < CH; i++) {
        int idx = base + i;
        s += (idx < NN) ? g_cnt[idx] : 0;
    }
    sT[tid] = s;
    __syncthreads();
    for (int off = 1; off < 1024; off <<= 1) {
        int v = (tid >= off) ? sT[tid - off] : 0;
        __syncthreads();
        sT[tid] += v;
        __syncthreads();
    }
    int run = (tid == 0) ? 0 : sT[tid - 1];
    for (int i = 0; i < CH; i++) {
        int idx = base + i;
        if (idx < NN) {
            g_rowptr[idx] = run;
            g_wofs[idx]   = run;
            run += g_cnt[idx];
        }
    }
    if (tid == 1023) g_rowptr[NN] = run;
}

__global__ void k_scatter(const int* __restrict__ src, const int* __restrict__ dst) {
    int e = blockIdx.x * blockDim.x + threadIdx.x;
    if (e < EE) {
        int p = atomicAdd(&g_wofs[dst[e]], 1);
        g_csrsrc[p] = src[e];
    }
}

// ---------------- layer-1 GEMM (din = 3) ----------------
__global__ void k_gemm3(const float* __restrict__ x,
                        const float* __restrict__ Wl,
                        const float* __restrict__ Wr) {
    int t = blockIdx.x * blockDim.x + threadIdx.x;
    int row = t >> 5, q = t & 31;
    if (row >= NN) return;
    float x0 = __ldg(&x[row * 3 + 0]);
    float x1 = __ldg(&x[row * 3 + 1]);
    float x2 = __ldg(&x[row * 3 + 2]);
    const float4* Wl4 = (const float4*)Wl;
    const float4* Wr4 = (const float4*)Wr;
    float4 a = __ldg(&Wl4[q]), b = __ldg(&Wl4[32 + q]), c = __ldg(&Wl4[64 + q]);
    float4 o;
    o.x = x0 * a.x + x1 * b.x + x2 * c.x;
    o.y = x0 * a.y + x1 * b.y + x2 * c.y;
    o.z = x0 * a.z + x1 * b.z + x2 * c.z;
    o.w = x0 * a.w + x1 * b.w + x2 * c.w;
    ((float4*)g_xl)[row * 32 + q] = o;
    a = __ldg(&Wr4[q]); b = __ldg(&Wr4[32 + q]); c = __ldg(&Wr4[64 + q]);
    o.x = x0 * a.x + x1 * b.x + x2 * c.x;
    o.y = x0 * a.y + x1 * b.y + x2 * c.y;
    o.z = x0 * a.z + x1 * b.z + x2 * c.z;
    o.w = x0 * a.w + x1 * b.w + x2 * c.w;
    ((float4*)g_xr)[row * 32 + q] = o;
}

// ---------------- layers 2/3 dual GEMM: [xl|xr](N,128) = g_x(N,64) @ W(64,128) ----------------
// grid.y: 0,1 -> Wl cols 0..63 / 64..127 ; 2,3 -> Wr
__global__ void k_gemm64(const float* __restrict__ Wl, const float* __restrict__ Wr) {
    __shared__ float As[64][68];   // padded: conflict-free scalar reads
    __shared__ float Ws[64][64];
    int by = blockIdx.y;
    const float* W = (by < 2) ? Wl : Wr;
    float* Cp = (by < 2) ? g_xl : g_xr;
    int colbase = (by & 1) * 64;
    int row0 = blockIdx.x * 64;
    int tid = threadIdx.x;  // 256

    for (int i = tid; i < 64 * 16; i += 256) {
        int r = i >> 4, k4 = i & 15;
        float4 v = make_float4(0.f, 0.f, 0.f, 0.f);
        if (row0 + r < NN) v = ((const float4*)g_x)[(row0 + r) * 16 + k4];
        *(float4*)&As[r][k4 * 4] = v;
    }
    for (int i = tid; i < 64 * 16; i += 256) {
        int k = i >> 4, c4 = i & 15;
        *(float4*)&Ws[k][c4 * 4] = __ldg((const float4*)(W + k * 128 + colbase + c4 * 4));
    }
    __syncthreads();

    int tx = tid & 15, ty = tid >> 4;
    float acc[4][4];
#pragma unroll
    for (int i = 0; i < 4; i++)
#pragma unroll
        for (int j = 0; j < 4; j++) acc[i][j] = 0.f;

#pragma unroll 8
    for (int k = 0; k < 64; k++) {
        float4 wv = *(float4*)&Ws[k][tx * 4];
        float a0 = As[ty * 4 + 0][k];
        float a1 = As[ty * 4 + 1][k];
        float a2 = As[ty * 4 + 2][k];
        float a3 = As[ty * 4 + 3][k];
        acc[0][0] += a0 * wv.x; acc[0][1] += a0 * wv.y; acc[0][2] += a0 * wv.z; acc[0][3] += a0 * wv.w;
        acc[1][0] += a1 * wv.x; acc[1][1] += a1 * wv.y; acc[1][2] += a1 * wv.z; acc[1][3] += a1 * wv.w;
        acc[2][0] += a2 * wv.x; acc[2][1] += a2 * wv.y; acc[2][2] += a2 * wv.z; acc[2][3] += a2 * wv.w;
        acc[3][0] += a3 * wv.x; acc[3][1] += a3 * wv.y; acc[3][2] += a3 * wv.z; acc[3][3] += a3 * wv.w;
    }
#pragma unroll
    for (int i = 0; i < 4; i++) {
        int r = row0 + ty * 4 + i;
        if (r < NN)
            *(float4*)&Cp[r * 128 + colbase + tx * 4] =
                make_float4(acc[i][0], acc[i][1], acc[i][2], acc[i][3]);
    }
}

// ---------------- aggregation: one warp per node, online softmax ----------------
// lane l handles channels [l*4, l*4+4) of the 128-wide [h0 c0..63 | h1 c0..63] row.
// lanes 0..15 = head 0, lanes 16..31 = head 1.
__global__ void k_agg(const float* __restrict__ att, const float* __restrict__ bias) {
    int gw = (blockIdx.x * blockDim.x + threadIdx.x) >> 5;
    int lane = threadIdx.x & 31;
    if (gw >= NN) return;
    int v = gw;
    const float4* xl4 = (const float4*)g_xl;
    float4 xrv  = ((const float4*)g_xr)[v * 32 + lane];
    float4 attv = __ldg(&((const float4*)att)[lane]);

    float m = -1e30f;
    float z = 0.f;
    float4 acc = make_float4(0.f, 0.f, 0.f, 0.f);

    int e0 = __ldg(&g_rowptr[v]);
    int e1 = __ldg(&g_rowptr[v + 1]);

    // e = e0-1 is the implicit self-loop (u = v)
    for (int e = e0 - 1; e < e1; e++) {
        int u = (e < e0) ? v : __ldg(&g_csrsrc[e]);
        float4 xlv = __ldg(&xl4[u * 32 + lane]);
        float tx = xlv.x + xrv.x, ty = xlv.y + xrv.y, tz = xlv.z + xrv.z, tw = xlv.w + xrv.w;
        tx = fmaxf(tx, 0.f) + NEG * fminf(tx, 0.f);
        ty = fmaxf(ty, 0.f) + NEG * fminf(ty, 0.f);
        tz = fmaxf(tz, 0.f) + NEG * fminf(tz, 0.f);
        tw = fmaxf(tw, 0.f) + NEG * fminf(tw, 0.f);
        float p = tx * attv.x + ty * attv.y + tz * attv.z + tw * attv.w;
        p += __shfl_xor_sync(0xffffffffu, p, 8);
        p += __shfl_xor_sync(0xffffffffu, p, 4);
        p += __shfl_xor_sync(0xffffffffu, p, 2);
        p += __shfl_xor_sync(0xffffffffu, p, 1);
        // online softmax update (per half-warp; replicated across its 16 lanes)
        float mn = fmaxf(m, p);
        float sc = __expf(m - mn);
        float a  = __expf(p - mn);
        z = z * sc + a;
        acc.x = acc.x * sc + a * xlv.x;
        acc.y = acc.y * sc + a * xlv.y;
        acc.z = acc.z * sc + a * xlv.z;
        acc.w = acc.w * sc + a * xlv.w;
        m = mn;
    }

    float inv = 1.f / z;
    float4 r;
    r.x = acc.x * inv; r.y = acc.y * inv; r.z = acc.z * inv; r.w = acc.w * inv;
    // mean over heads: partner lane is lane^16 (same channels, other head)
    r.x += __shfl_xor_sync(0xffffffffu, r.x, 16);
    r.y += __shfl_xor_sync(0xffffffffu, r.y, 16);
    r.z += __shfl_xor_sync(0xffffffffu, r.z, 16);
    r.w += __shfl_xor_sync(0xffffffffu, r.w, 16);
    if (lane < 16) {
        float4 b4 = __ldg(&((const float4*)bias)[lane]);
        float4 o;
        o.x = 0.5f * r.x + b4.x;
        o.y = 0.5f * r.y + b4.y;
        o.z = 0.5f * r.z + b4.z;
        o.w = 0.5f * r.w + b4.w;
        ((float4*)g_y)[v * 16 + lane] = o;
    }
}

// ---------------- GraphNorm stats + apply ----------------
__global__ void k_zero_stats() {
    int i = threadIdx.x;
    if (i < 64) { g_sum[i] = 0.f; g_sumsq[i] = 0.f; }
}

__global__ void k_stats() {
    int col  = threadIdx.x & 63;
    int rgrp = threadIdx.x >> 6;  // 0..3
    int row  = blockIdx.x * 4 + rgrp;
    int stride = gridDim.x * 4;
    float s = 0.f, s2 = 0.f;
    for (int r = row; r < NN; r += stride) {
        float v = g_y[r * 64 + col];
        s += v;
        s2 += v * v;
    }
    __shared__ float ss[256], ss2[256];
    ss[threadIdx.x] = s;
    ss2[threadIdx.x] = s2;
    __syncthreads();
    if (rgrp == 0) {
        s  = ss[col]  + ss[col + 64]  + ss[col + 128]  + ss[col + 192];
        s2 = ss2[col] + ss2[col + 64] + ss2[col + 128] + ss2[col + 192];
        atomicAdd(&g_sum[col], s);
        atomicAdd(&g_sumsq[col], s2);
    }
}

__global__ void k_apply(const float* __restrict__ gw, const float* __restrict__ gb,
                        const float* __restrict__ gm, float* __restrict__ xo) {
    int t = blockIdx.x * blockDim.x + threadIdx.x;
    if (t >= NN * 64) return;
    int col = t & 63;
    const float invn = 1.f / (float)NN;
    float mu  = g_sum[col] * invn;
    float ex2 = g_sumsq[col] * invn;
    float gmv = __ldg(&gm[col]);
    // var of o = y - gm*mu:  E[y^2] - gm*(2-gm)*mu^2
    float var = ex2 - gmv * (2.f - gmv) * mu * mu;
    float o = g_y[t] - gmv * mu;
    float r = __ldg(&gw[col]) * o * rsqrtf(var + EPSV) + __ldg(&gb[col]);
    xo[t] = fmaxf(r, 0.f);
}

// ---------------- launch ----------------
extern "C" void kernel_launch(void* const* d_in, const int* in_sizes, int n_in,
                              void* d_out, int out_size) {
    const float* x  = (const float*)d_in[0];
    const int*   ei = (const int*)d_in[1];
    const float *Wl[3], *Wr[3], *att[3], *bb[3], *gw[3], *gb[3], *gm[3];
    for (int i = 0; i < 3; i++) {
        int o = 2 + i * 7;
        Wl[i]  = (const float*)d_in[o + 0];
        Wr[i]  = (const float*)d_in[o + 1];
        att[i] = (const float*)d_in[o + 2];
        bb[i]  = (const float*)d_in[o + 3];
        gw[i]  = (const float*)d_in[o + 4];
        gb[i]  = (const float*)d_in[o + 5];
        gm[i]  = (const float*)d_in[o + 6];
    }
    const int* srcp = ei;
    const int* dstp = ei + EE;

    float* gx_ptr = nullptr;
    cudaGetSymbolAddress((void**)&gx_ptr, g_x);

    // CSR build (dst is a launch input; rebuilt every call, graph-capturable)
    k_zero_cnt<<<(NN + 255) / 256, 256>>>();
    k_hist<<<(EE + 255) / 256, 256>>>(dstp);
    k_scan<<<1, 1024>>>();
    k_scatter<<<(EE + 255) / 256, 256>>>(srcp, dstp);

    dim3 ggemm((NN + 63) / 64, 4);
    int agg_blocks = (NN * 32 + 255) / 256;
    int app_blocks = (NN * 64 + 255) / 256;

    // layer 1
    k_gemm3<<<(NN * 32 + 255) / 256, 256>>>(x, Wl[0], Wr[0]);
    k_agg<<<agg_blocks, 256>>>(att[0], bb[0]);
    k_zero_stats<<<1, 64>>>();
    k_stats<<<128, 256>>>();
    k_apply<<<app_blocks, 256>>>(gw[0], gb[0], gm[0], gx_ptr);

    // layer 2
    k_gemm64<<<ggemm, 256>>>(Wl[1], Wr[1]);
    k_agg<<<agg_blocks, 256>>>(att[1], bb[1]);
    k_zero_stats<<<1, 64>>>();
    k_stats<<<128, 256>>>();
    k_apply<<<app_blocks, 256>>>(gw[1], gb[1], gm[1], gx_ptr);

    // layer 3 (apply writes final output)
    k_gemm64<<<ggemm, 256>>>(Wl[2], Wr[2]);
    k_agg<<<agg_blocks, 256>>>(att[2], bb[2]);
    k_zero_stats<<<1, 64>>>();
    k_stats<<<128, 256>>>();
    k_apply<<<app_blocks, 256>>>(gw[2], gb[2], gm[2], (float*)d_out);
}